// round 7
// baseline (speedup 1.0000x reference)
#include <cuda_runtime.h>
#include <cuda_bf16.h>
#include <stdint.h>
#include <math.h>

// LSTM cell: gates = x@W^T + pre_h@U^T via mma.sync bf16 3-term split.
// N = 128 = 32 units x 4 gates, gate-minor (n = u*4 + g).
// 3-stage cp.async pipeline, one barrier per chunk, 2 CTAs/SM.
// R7: term-outer MMA order (no serial acc chains) + early first-LDSM per chunk.

#define NBATCH 4096
#define NUNITS 2048
#define KD     2048
#define BM 128
#define BK 32
#define NCH 128               // 2 phases * (2048/32)
#define TILEB (128*64)        // 8192 B
#define STAGEB (4*TILEB)      // Ah, Al, Bh, Bl = 32768 B
#define SMEMB (3*STAGEB)      // 98304 B

// -------- bf16 hi/lo scratch --------
__device__ __align__(128) __nv_bfloat16 g_xh[(size_t)NBATCH*KD];
__device__ __align__(128) __nv_bfloat16 g_xl[(size_t)NBATCH*KD];
__device__ __align__(128) __nv_bfloat16 g_hh[(size_t)NBATCH*KD];
__device__ __align__(128) __nv_bfloat16 g_hl[(size_t)NBATCH*KD];
__device__ __align__(128) __nv_bfloat16 g_wh[(size_t)4*NUNITS*KD];
__device__ __align__(128) __nv_bfloat16 g_wl[(size_t)4*NUNITS*KD];
__device__ __align__(128) __nv_bfloat16 g_uh[(size_t)4*NUNITS*KD];
__device__ __align__(128) __nv_bfloat16 g_ul[(size_t)4*NUNITS*KD];

__device__ __forceinline__ uint32_t smem_u32(const void* p) {
    uint32_t a;
    asm("{ .reg .u64 t; cvta.to.shared.u64 t, %1; cvt.u32.u64 %0, t; }" : "=r"(a) : "l"(p));
    return a;
}
__device__ __forceinline__ void cp16(uint32_t dst, const void* src) {
    asm volatile("cp.async.cg.shared.global [%0], [%1], 16;" :: "r"(dst), "l"(src));
}
__device__ __forceinline__ void ldsm4(uint32_t& r0, uint32_t& r1, uint32_t& r2, uint32_t& r3,
                                      uint32_t addr) {
    asm volatile("ldmatrix.sync.aligned.m8n8.x4.shared.b16 {%0,%1,%2,%3}, [%4];"
                 : "=r"(r0), "=r"(r1), "=r"(r2), "=r"(r3) : "r"(addr));
}
__device__ __forceinline__ void mma16816(float* d, const uint32_t* a, const uint32_t* b) {
    asm volatile(
        "mma.sync.aligned.m16n8k16.row.col.f32.bf16.bf16.f32 "
        "{%0,%1,%2,%3}, {%4,%5,%6,%7}, {%8,%9}, {%0,%1,%2,%3};"
        : "+f"(d[0]), "+f"(d[1]), "+f"(d[2]), "+f"(d[3])
        : "r"(a[0]), "r"(a[1]), "r"(a[2]), "r"(a[3]), "r"(b[0]), "r"(b[1]));
}

// one chunk of cp.async: A_hi/A_lo/B_hi/B_lo tiles (128 rows x 32 bf16 each)
__device__ __forceinline__ void load_chunk(int c, uint32_t st, int bm, int bu, int tid) {
    const int koff = (c & 63) * BK;
    const __nv_bfloat16 *Ah, *Al, *Bh, *Bl;
    if (c < 64) { Ah = g_xh; Al = g_xl; Bh = g_wh; Bl = g_wl; }
    else        { Ah = g_hh; Al = g_hl; Bh = g_uh; Bl = g_ul; }
    #pragma unroll
    for (int i = 0; i < 2; ++i) {
        int e = i * 256 + tid;                 // 512 16B units per tile
        int r = e >> 2, ch = e & 3;
        uint32_t d = st + r * 64 + (((ch ^ ((r >> 1) & 3))) << 4);
        size_t ga = (size_t)(bm + r) * KD + koff + ch * 8;
        cp16(d, Ah + ga);
        cp16(d + TILEB, Al + ga);
        int u = r >> 2, g = r & 3;             // B row r: n = u*4 + g (gate-minor)
        size_t gb = ((size_t)(g * NUNITS + bu + u)) * KD + koff + ch * 8;
        cp16(d + 2 * TILEB, Bh + gb);
        cp16(d + 3 * TILEB, Bl + gb);
    }
}

__global__ void __launch_bounds__(256, 2)
lstm_mma(const float* __restrict__ pre_c, float* __restrict__ out)
{
    extern __shared__ char smem[];
    const uint32_t sb = smem_u32(smem);
    const int tid = threadIdx.x, lane = tid & 31, wid = tid >> 5;
    const int bm = blockIdx.y * BM, bu = blockIdx.x * 32;
    const int wm = (wid >> 2) * 64, wn = (wid & 3) * 32;

    float acc[4][4][4];
    #pragma unroll
    for (int i = 0; i < 4; ++i)
        #pragma unroll
        for (int j = 0; j < 4; ++j)
            #pragma unroll
            for (int k = 0; k < 4; ++k) acc[i][j][k] = 0.f;

    load_chunk(0, sb, bm, bu, tid);
    asm volatile("cp.async.commit_group;" ::: "memory");
    load_chunk(1, sb + STAGEB, bm, bu, tid);
    asm volatile("cp.async.commit_group;" ::: "memory");

    // A frag: row = wm + i*16 + (lane&15); logical 16B chunk ch = (lane>>4) + 2s
    const int rA = wm + (lane & 15);
    const uint32_t aBase = (uint32_t)rA * 64;
    const int selA = (rA >> 1) & 3;
    const int chA0 = lane >> 4;
    // B frag: row = wn + jj*16 + ((lane>>4)<<3) + (lane&7); ch = ((lane>>3)&1) + 2s
    const int rB = wn + (((lane >> 4) << 3) + (lane & 7));
    const uint32_t bBase = (uint32_t)rB * 64;
    const int selB = (rB >> 1) & 3;
    const int chB0 = (lane >> 3) & 1;

    uint32_t stv  = sb;                  // stage holding chunk c
    uint32_t stn  = sb + STAGEB;         // chunk c+1
    uint32_t stn2 = sb + 2 * STAGEB;     // chunk c+2 (to be filled)

    #pragma unroll 1
    for (int c = 0; c < NCH; ++c) {
        asm volatile("cp.async.wait_group 1;" ::: "memory");  // chunk c resident
        __syncthreads();   // visible to all; everyone done with stn2's old chunk

        const uint32_t aH = stv + aBase;
        const uint32_t bH = stv + 2 * TILEB + bBase;

        // ---- early s=0 fragment loads (start tensor work ASAP) ----
        uint32_t ah[4][4], al[4][4], bh[4][2], bl[4][2];
        {
            const uint32_t offB0 = (uint32_t)((chB0 ^ selB) << 4);
            const uint32_t offA0 = (uint32_t)((chA0 ^ selA) << 4);
            #pragma unroll
            for (int jj = 0; jj < 2; ++jj) {
                uint32_t ad = bH + jj * 1024 + offB0;
                ldsm4(bh[2*jj][0], bh[2*jj][1], bh[2*jj+1][0], bh[2*jj+1][1], ad);
                ldsm4(bl[2*jj][0], bl[2*jj][1], bl[2*jj+1][0], bl[2*jj+1][1], ad + TILEB);
            }
            #pragma unroll
            for (int i = 0; i < 4; ++i) {
                uint32_t ad = aH + i * 1024 + offA0;
                ldsm4(ah[i][0], ah[i][1], ah[i][2], ah[i][3], ad);
                ldsm4(al[i][0], al[i][1], al[i][2], al[i][3], ad + TILEB);
            }
        }
        // ---- issue next chunk's loads while s=0 MMAs run ----
        if (c + 2 < NCH) load_chunk(c + 2, stn2, bm, bu, tid);
        asm volatile("cp.async.commit_group;" ::: "memory");

        #pragma unroll
        for (int s = 0; s < 2; ++s) {
            if (s == 1) {      // load s=1 fragments
                const uint32_t offB = (uint32_t)(((chB0 + 2) ^ selB) << 4);
                const uint32_t offA = (uint32_t)(((chA0 + 2) ^ selA) << 4);
                #pragma unroll
                for (int jj = 0; jj < 2; ++jj) {
                    uint32_t ad = bH + jj * 1024 + offB;
                    ldsm4(bh[2*jj][0], bh[2*jj][1], bh[2*jj+1][0], bh[2*jj+1][1], ad);
                    ldsm4(bl[2*jj][0], bl[2*jj][1], bl[2*jj+1][0], bl[2*jj+1][1], ad + TILEB);
                }
                #pragma unroll
                for (int i = 0; i < 4; ++i) {
                    uint32_t ad = aH + i * 1024 + offA;
                    ldsm4(ah[i][0], ah[i][1], ah[i][2], ah[i][3], ad);
                    ldsm4(al[i][0], al[i][1], al[i][2], al[i][3], ad + TILEB);
                }
            }
            // term-outer: consecutive MMAs hit different accumulators
            #pragma unroll
            for (int i = 0; i < 4; ++i)
                #pragma unroll
                for (int j = 0; j < 4; ++j)
                    mma16816(acc[i][j], ah[i], bh[j]);
            #pragma unroll
            for (int i = 0; i < 4; ++i)
                #pragma unroll
                for (int j = 0; j < 4; ++j)
                    mma16816(acc[i][j], ah[i], bl[j]);
            #pragma unroll
            for (int i = 0; i < 4; ++i)
                #pragma unroll
                for (int j = 0; j < 4; ++j)
                    mma16816(acc[i][j], al[i], bh[j]);
        }
        uint32_t t = stv; stv = stn; stn = stn2; stn2 = t;   // rotate stages
    }

    // ---------------- fused LSTM epilogue ----------------
    // prefetch this thread's pre_c values (hide DRAM latency under staging)
    const size_t CO = (size_t)NBATCH * NUNITS;
    float pcv[16];
    #pragma unroll
    for (int i = 0; i < 16; ++i) {
        int idx = i * 256 + tid;
        int m = idx >> 5, u = idx & 31;
        pcv[i] = pre_c[(size_t)(bm + m) * NUNITS + bu + u];
    }
    __syncthreads();
    float* S = (float*)smem;                 // [8 warps][64 m][32 n-local]
    const uint32_t base = wid * 2048;
    #pragma unroll
    for (int i = 0; i < 4; ++i)
        #pragma unroll
        for (int j = 0; j < 4; ++j) {
            int r0 = i * 16 + (lane >> 2), c0 = j * 8 + (lane & 3) * 2;
            *(float2*)&S[base + r0 * 32 + c0]       = make_float2(acc[i][j][0], acc[i][j][1]);
            *(float2*)&S[base + (r0 + 8) * 32 + c0] = make_float2(acc[i][j][2], acc[i][j][3]);
        }
    __syncthreads();

    #pragma unroll
    for (int i = 0; i < 16; ++i) {
        int idx = i * 256 + tid;
        int m = idx >> 5, u = idx & 31;
        int wreg = (m >> 6) * 4 + (u >> 3);
        float4 gt = *(float4*)&S[wreg * 2048 + (m & 63) * 32 + (u & 7) * 4];
        float it = 1.f / (1.f + __expf(-gt.x));
        float ft = 1.f / (1.f + __expf(-gt.y));
        float ot = 1.f / (1.f + __expf(-gt.z));
        float nt = tanhf(gt.w);
        size_t o = (size_t)(bm + m) * NUNITS + bu + u;
        float cc = ft * pcv[i] + it * nt;
        float hh = ot * tanhf(cc);
        out[o]      = hh;
        out[CO + o] = cc;
    }
}

// -------- fp32 -> bf16 hi/lo split, all 4 tensors in one launch --------
__global__ void split_all(const float* __restrict__ x, const float* __restrict__ ph,
                          const float* __restrict__ W, const float* __restrict__ U)
{
    const int SEG = NBATCH * KD / 4;               // 2M float4 per x-like tensor
    int i = blockIdx.x * 256 + threadIdx.x;
    const float* s; __nv_bfloat16 *hi, *lo; int off;
    if (i < SEG)            { s = x;  hi = g_xh; lo = g_xl; off = i; }
    else if (i < 2 * SEG)   { s = ph; hi = g_hh; lo = g_hl; off = i - SEG; }
    else if (i < 4 * SEG)   { s = W;  hi = g_wh; lo = g_wl; off = i - 2 * SEG; }
    else                    { s = U;  hi = g_uh; lo = g_ul; off = i - 4 * SEG; }
    float4 v = reinterpret_cast<const float4*>(s)[off];
    float f[4] = {v.x, v.y, v.z, v.w};
    unsigned short hs[4], ls[4];
    #pragma unroll
    for (int k = 0; k < 4; ++k) {
        __nv_bfloat16 h = __float2bfloat16(f[k]);
        __nv_bfloat16 l = __float2bfloat16(f[k] - __bfloat162float(h));
        hs[k] = *reinterpret_cast<unsigned short*>(&h);
        ls[k] = *reinterpret_cast<unsigned short*>(&l);
    }
    reinterpret_cast<ushort4*>(hi)[off] = make_ushort4(hs[0], hs[1], hs[2], hs[3]);
    reinterpret_cast<ushort4*>(lo)[off] = make_ushort4(ls[0], ls[1], ls[2], ls[3]);
}

extern "C" void kernel_launch(void* const* d_in, const int* in_sizes, int n_in,
                              void* d_out, int out_size)
{
    const float* pre_layer = (const float*)d_in[0];  // (2, 4096, 2048)
    const float* x         = (const float*)d_in[1];  // (4096, 2048)
    const float* W         = (const float*)d_in[2];  // (4, 2048, 2048)
    const float* U         = (const float*)d_in[3];  // (4, 2048, 2048)
    float* out             = (float*)d_out;

    const int SEG = NBATCH * KD / 4;                 // 2M
    const int total = 6 * SEG;                       // x(1) + h(1) + W(2) + U(2)
    split_all<<<total / 256, 256>>>(x, pre_layer, W, U);

    cudaFuncSetAttribute(lstm_mma, cudaFuncAttributeMaxDynamicSharedMemorySize, SMEMB);
    const float* pre_c = pre_layer + (size_t)NBATCH * NUNITS;
    lstm_mma<<<dim3(NUNITS / 32, NBATCH / BM), 256, SMEMB>>>(pre_c, out);
}

// round 9
// speedup vs baseline: 1.1769x; 1.1769x over previous
#include <cuda_runtime.h>
#include <cuda_bf16.h>
#include <stdint.h>
#include <math.h>

// LSTM cell: gates = x@W^T + pre_h@U^T via mma.sync bf16 3-term split.
// N = 128 = 32 units x 4 gates, gate-minor (n = u*4 + g).
// R9: lock-free 3-stage mbarrier producer/consumer ring (cp.async.mbarrier.
// arrive.NOINC — R8 deadlocked on the inc variant), 2 CTAs/SM.

#define NBATCH 4096
#define NUNITS 2048
#define KD     2048
#define BM 128
#define BK 32
#define NCH 128               // 2 phases * (2048/32)
#define TILEB (128*64)        // 8192 B
#define STAGEB (4*TILEB)      // Ah, Al, Bh, Bl = 32768 B
#define SMEMB (3*STAGEB + 64) // stages + mbarriers

// -------- bf16 hi/lo scratch --------
__device__ __align__(128) __nv_bfloat16 g_xh[(size_t)NBATCH*KD];
__device__ __align__(128) __nv_bfloat16 g_xl[(size_t)NBATCH*KD];
__device__ __align__(128) __nv_bfloat16 g_hh[(size_t)NBATCH*KD];
__device__ __align__(128) __nv_bfloat16 g_hl[(size_t)NBATCH*KD];
__device__ __align__(128) __nv_bfloat16 g_wh[(size_t)4*NUNITS*KD];
__device__ __align__(128) __nv_bfloat16 g_wl[(size_t)4*NUNITS*KD];
__device__ __align__(128) __nv_bfloat16 g_uh[(size_t)4*NUNITS*KD];
__device__ __align__(128) __nv_bfloat16 g_ul[(size_t)4*NUNITS*KD];

__device__ __forceinline__ uint32_t smem_u32(const void* p) {
    uint32_t a;
    asm("{ .reg .u64 t; cvta.to.shared.u64 t, %1; cvt.u32.u64 %0, t; }" : "=r"(a) : "l"(p));
    return a;
}
__device__ __forceinline__ void cp16(uint32_t dst, const void* src) {
    asm volatile("cp.async.cg.shared.global [%0], [%1], 16;" :: "r"(dst), "l"(src));
}
__device__ __forceinline__ void mbar_init(uint32_t m, uint32_t cnt) {
    asm volatile("mbarrier.init.shared.b64 [%0], %1;" :: "r"(m), "r"(cnt) : "memory");
}
__device__ __forceinline__ void mbar_arrive(uint32_t m) {
    asm volatile("mbarrier.arrive.shared.b64 _, [%0];" :: "r"(m) : "memory");
}
__device__ __forceinline__ void cp_arrive_noinc(uint32_t m) {
    asm volatile("cp.async.mbarrier.arrive.noinc.shared.b64 [%0];" :: "r"(m) : "memory");
}
__device__ __forceinline__ void mbar_wait(uint32_t m, uint32_t parity) {
    asm volatile(
        "{\n\t.reg .pred P;\n\t"
        "LAB%=:\n\t"
        "mbarrier.try_wait.parity.acquire.cta.shared::cta.b64 P, [%0], %1, 0x989680;\n\t"
        "@!P bra LAB%=;\n\t}"
        :: "r"(m), "r"(parity) : "memory");
}
__device__ __forceinline__ void ldsm4(uint32_t& r0, uint32_t& r1, uint32_t& r2, uint32_t& r3,
                                      uint32_t addr) {
    asm volatile("ldmatrix.sync.aligned.m8n8.x4.shared.b16 {%0,%1,%2,%3}, [%4];"
                 : "=r"(r0), "=r"(r1), "=r"(r2), "=r"(r3) : "r"(addr));
}
__device__ __forceinline__ void mma16816(float* d, const uint32_t* a, const uint32_t* b) {
    asm volatile(
        "mma.sync.aligned.m16n8k16.row.col.f32.bf16.bf16.f32 "
        "{%0,%1,%2,%3}, {%4,%5,%6,%7}, {%8,%9}, {%0,%1,%2,%3};"
        : "+f"(d[0]), "+f"(d[1]), "+f"(d[2]), "+f"(d[3])
        : "r"(a[0]), "r"(a[1]), "r"(a[2]), "r"(a[3]), "r"(b[0]), "r"(b[1]));
}

// one chunk of cp.async: A_hi/A_lo/B_hi/B_lo tiles (128 rows x 32 bf16 each)
__device__ __forceinline__ void load_chunk(int c, uint32_t st, int bm, int bu, int tid) {
    const int koff = (c & 63) * BK;
    const __nv_bfloat16 *Ah, *Al, *Bh, *Bl;
    if (c < 64) { Ah = g_xh; Al = g_xl; Bh = g_wh; Bl = g_wl; }
    else        { Ah = g_hh; Al = g_hl; Bh = g_uh; Bl = g_ul; }
    #pragma unroll
    for (int i = 0; i < 2; ++i) {
        int e = i * 256 + tid;                 // 512 16B units per tile
        int r = e >> 2, ch = e & 3;
        uint32_t d = st + r * 64 + (((ch ^ ((r >> 1) & 3))) << 4);
        size_t ga = (size_t)(bm + r) * KD + koff + ch * 8;
        cp16(d, Ah + ga);
        cp16(d + TILEB, Al + ga);
        int u = r >> 2, g = r & 3;             // B row r: n = u*4 + g (gate-minor)
        size_t gb = ((size_t)(g * NUNITS + bu + u)) * KD + koff + ch * 8;
        cp16(d + 2 * TILEB, Bh + gb);
        cp16(d + 3 * TILEB, Bl + gb);
    }
}

__global__ void __launch_bounds__(256, 2)
lstm_mma(const float* __restrict__ pre_c, float* __restrict__ out)
{
    extern __shared__ char smem[];
    const uint32_t sb = smem_u32(smem);
    const int tid = threadIdx.x, lane = tid & 31, wid = tid >> 5;
    const int bm = blockIdx.y * BM, bu = blockIdx.x * 32;
    const int wm = (wid >> 2) * 64, wn = (wid & 3) * 32;

    const uint32_t mb = sb + 3 * STAGEB;       // mbarrier block
    // full[s] = mb + 8*s ; free[s] = mb + 24 + 8*s
    if (tid == 0) {
        #pragma unroll
        for (int s = 0; s < 3; ++s) { mbar_init(mb + 8 * s, 256); mbar_init(mb + 24 + 8 * s, 256); }
    }
    __syncthreads();

    float acc[4][4][4];
    #pragma unroll
    for (int i = 0; i < 4; ++i)
        #pragma unroll
        for (int j = 0; j < 4; ++j)
            #pragma unroll
            for (int k = 0; k < 4; ++k) acc[i][j][k] = 0.f;

    // prologue: load chunks 0 and 1, arm full[0], full[1]
    load_chunk(0, sb, bm, bu, tid);
    cp_arrive_noinc(mb + 0);
    load_chunk(1, sb + STAGEB, bm, bu, tid);
    cp_arrive_noinc(mb + 8);

    // A frag: row = wm + i*16 + (lane&15); logical 16B chunk ch = (lane>>4) + 2s
    const int rA = wm + (lane & 15);
    const uint32_t aBase = (uint32_t)rA * 64;
    const int selA = (rA >> 1) & 3;
    const int chA0 = lane >> 4;
    // B frag: row = wn + ((lane>>4)<<3) + (lane&7); ch = ((lane>>3)&1) + 2s
    const int rB = wn + (((lane >> 4) << 3) + (lane & 7));
    const uint32_t bBase = (uint32_t)rB * 64;
    const int selB = (rB >> 1) & 3;
    const int chB0 = (lane >> 3) & 1;

    #pragma unroll 1
    for (int c = 0; c < NCH; ++c) {
        const int s = c % 3;
        const uint32_t stv = sb + s * STAGEB;

        // ---- consume chunk c ----
        mbar_wait(mb + 8 * s, (uint32_t)((c / 3) & 1));

        const uint32_t aH = stv + aBase;
        const uint32_t bH = stv + 2 * TILEB + bBase;
        #pragma unroll
        for (int sk = 0; sk < 2; ++sk) {
            const uint32_t offB = (uint32_t)(((chB0 + 2 * sk) ^ selB) << 4);
            const uint32_t offA = (uint32_t)(((chA0 + 2 * sk) ^ selA) << 4);
            uint32_t bh[4][2], bl[4][2];
            #pragma unroll
            for (int jj = 0; jj < 2; ++jj) {
                uint32_t ad = bH + jj * 1024 + offB;
                ldsm4(bh[2*jj][0], bh[2*jj][1], bh[2*jj+1][0], bh[2*jj+1][1], ad);
                ldsm4(bl[2*jj][0], bl[2*jj][1], bl[2*jj+1][0], bl[2*jj+1][1], ad + TILEB);
            }
            #pragma unroll
            for (int i = 0; i < 4; ++i) {
                uint32_t ah[4], al[4];
                uint32_t ad = aH + i * 1024 + offA;
                ldsm4(ah[0], ah[1], ah[2], ah[3], ad);
                ldsm4(al[0], al[1], al[2], al[3], ad + TILEB);
                #pragma unroll
                for (int j = 0; j < 4; ++j) {
                    mma16816(acc[i][j], ah, bh[j]);
                    mma16816(acc[i][j], ah, bl[j]);
                    mma16816(acc[i][j], al, bh[j]);
                }
            }
        }
        mbar_arrive(mb + 24 + 8 * s);          // stage s free (this thread)

        // ---- produce chunk c+2 ----
        const int cp = c + 2;
        if (cp < NCH) {
            const int s2 = cp % 3;
            if (cp >= 3) mbar_wait(mb + 24 + 8 * s2, (uint32_t)(((cp / 3) - 1) & 1));
            load_chunk(cp, sb + s2 * STAGEB, bm, bu, tid);
            cp_arrive_noinc(mb + 8 * s2);
        }
    }
    __syncthreads();   // all warps done; smem reusable

    // ---------------- fused LSTM epilogue ----------------
    const size_t CO = (size_t)NBATCH * NUNITS;
    float pcv[16];
    #pragma unroll
    for (int i = 0; i < 16; ++i) {
        int idx = i * 256 + tid;
        int m = idx >> 5, u = idx & 31;
        pcv[i] = pre_c[(size_t)(bm + m) * NUNITS + bu + u];
    }
    float* S = (float*)smem;                 // [8 warps][64 m][32 n-local]
    const uint32_t base = wid * 2048;
    #pragma unroll
    for (int i = 0; i < 4; ++i)
        #pragma unroll
        for (int j = 0; j < 4; ++j) {
            int r0 = i * 16 + (lane >> 2), c0 = j * 8 + (lane & 3) * 2;
            *(float2*)&S[base + r0 * 32 + c0]       = make_float2(acc[i][j][0], acc[i][j][1]);
            *(float2*)&S[base + (r0 + 8) * 32 + c0] = make_float2(acc[i][j][2], acc[i][j][3]);
        }
    __syncthreads();

    #pragma unroll
    for (int i = 0; i < 16; ++i) {
        int idx = i * 256 + tid;
        int m = idx >> 5, u = idx & 31;
        int wreg = (m >> 6) * 4 + (u >> 3);
        float4 gt = *(float4*)&S[wreg * 2048 + (m & 63) * 32 + (u & 7) * 4];
        float it = 1.f / (1.f + __expf(-gt.x));
        float ft = 1.f / (1.f + __expf(-gt.y));
        float ot = 1.f / (1.f + __expf(-gt.z));
        float nt = tanhf(gt.w);
        size_t o = (size_t)(bm + m) * NUNITS + bu + u;
        float cc = ft * pcv[i] + it * nt;
        float hh = ot * tanhf(cc);
        out[o]      = hh;
        out[CO + o] = cc;
    }
}

// -------- fp32 -> bf16 hi/lo split, all 4 tensors in one launch --------
__global__ void split_all(const float* __restrict__ x, const float* __restrict__ ph,
                          const float* __restrict__ W, const float* __restrict__ U)
{
    const int SEG = NBATCH * KD / 4;               // 2M float4 per x-like tensor
    int i = blockIdx.x * 256 + threadIdx.x;
    const float* s; __nv_bfloat16 *hi, *lo; int off;
    if (i < SEG)            { s = x;  hi = g_xh; lo = g_xl; off = i; }
    else if (i < 2 * SEG)   { s = ph; hi = g_hh; lo = g_hl; off = i - SEG; }
    else if (i < 4 * SEG)   { s = W;  hi = g_wh; lo = g_wl; off = i - 2 * SEG; }
    else                    { s = U;  hi = g_uh; lo = g_ul; off = i - 4 * SEG; }
    float4 v = reinterpret_cast<const float4*>(s)[off];
    float f[4] = {v.x, v.y, v.z, v.w};
    unsigned short hs[4], ls[4];
    #pragma unroll
    for (int k = 0; k < 4; ++k) {
        __nv_bfloat16 h = __float2bfloat16(f[k]);
        __nv_bfloat16 l = __float2bfloat16(f[k] - __bfloat162float(h));
        hs[k] = *reinterpret_cast<unsigned short*>(&h);
        ls[k] = *reinterpret_cast<unsigned short*>(&l);
    }
    reinterpret_cast<ushort4*>(hi)[off] = make_ushort4(hs[0], hs[1], hs[2], hs[3]);
    reinterpret_cast<ushort4*>(lo)[off] = make_ushort4(ls[0], ls[1], ls[2], ls[3]);
}

extern "C" void kernel_launch(void* const* d_in, const int* in_sizes, int n_in,
                              void* d_out, int out_size)
{
    const float* pre_layer = (const float*)d_in[0];  // (2, 4096, 2048)
    const float* x         = (const float*)d_in[1];  // (4096, 2048)
    const float* W         = (const float*)d_in[2];  // (4, 2048, 2048)
    const float* U         = (const float*)d_in[3];  // (4, 2048, 2048)
    float* out             = (float*)d_out;

    const int SEG = NBATCH * KD / 4;                 // 2M
    const int total = 6 * SEG;                       // x(1) + h(1) + W(2) + U(2)
    split_all<<<total / 256, 256>>>(x, pre_layer, W, U);

    cudaFuncSetAttribute(lstm_mma, cudaFuncAttributeMaxDynamicSharedMemorySize, SMEMB);
    const float* pre_c = pre_layer + (size_t)NBATCH * NUNITS;
    lstm_mma<<<dim3(NUNITS / 32, NBATCH / BM), 256, SMEMB>>>(pre_c, out);
}

// round 10
// speedup vs baseline: 1.7208x; 1.4621x over previous
#include <cuda_runtime.h>
#include <cuda_fp16.h>
#include <stdint.h>
#include <math.h>

// LSTM cell: gates = x@W^T + pre_h@U^T via mma.sync fp16 2-term split.
//   activations a = ah + al (fp16 pair, exact); weights rounded to fp16 bh.
//   acc = ah*bh + al*bh = a*bh exactly; error only a*(b-bh) ~ 2^-12 relative.
// N = 128 = 32 units x 4 gates, gate-minor (n = u*4 + g).
// 4-stage lock-free mbarrier ring, 2 CTAs/SM.

#define NBATCH 4096
#define NUNITS 2048
#define KD     2048
#define BM 128
#define BK 32
#define NCH 128                // 2 phases * (2048/32)
#define NSTG 4
#define TILEB (128*64)         // 8192 B (128 rows x 32 fp16)
#define STAGEB (3*TILEB)       // Ah, Al, Bh = 24576 B
#define SMEMB (NSTG*STAGEB + 64)

// -------- fp16 scratch --------
__device__ __align__(128) __half g_xh[(size_t)NBATCH*KD];
__device__ __align__(128) __half g_xl[(size_t)NBATCH*KD];
__device__ __align__(128) __half g_hh[(size_t)NBATCH*KD];
__device__ __align__(128) __half g_hl[(size_t)NBATCH*KD];
__device__ __align__(128) __half g_wh[(size_t)4*NUNITS*KD];
__device__ __align__(128) __half g_uh[(size_t)4*NUNITS*KD];

__device__ __forceinline__ uint32_t smem_u32(const void* p) {
    uint32_t a;
    asm("{ .reg .u64 t; cvta.to.shared.u64 t, %1; cvt.u32.u64 %0, t; }" : "=r"(a) : "l"(p));
    return a;
}
__device__ __forceinline__ void cp16(uint32_t dst, const void* src) {
    asm volatile("cp.async.cg.shared.global [%0], [%1], 16;" :: "r"(dst), "l"(src));
}
__device__ __forceinline__ void mbar_init(uint32_t m, uint32_t cnt) {
    asm volatile("mbarrier.init.shared.b64 [%0], %1;" :: "r"(m), "r"(cnt) : "memory");
}
__device__ __forceinline__ void mbar_arrive(uint32_t m) {
    asm volatile("mbarrier.arrive.shared.b64 _, [%0];" :: "r"(m) : "memory");
}
__device__ __forceinline__ void cp_arrive_noinc(uint32_t m) {
    asm volatile("cp.async.mbarrier.arrive.noinc.shared.b64 [%0];" :: "r"(m) : "memory");
}
__device__ __forceinline__ void mbar_wait(uint32_t m, uint32_t parity) {
    asm volatile(
        "{\n\t.reg .pred P;\n\t"
        "LAB%=:\n\t"
        "mbarrier.try_wait.parity.acquire.cta.shared::cta.b64 P, [%0], %1, 0x989680;\n\t"
        "@!P bra LAB%=;\n\t}"
        :: "r"(m), "r"(parity) : "memory");
}
__device__ __forceinline__ void ldsm4(uint32_t& r0, uint32_t& r1, uint32_t& r2, uint32_t& r3,
                                      uint32_t addr) {
    asm volatile("ldmatrix.sync.aligned.m8n8.x4.shared.b16 {%0,%1,%2,%3}, [%4];"
                 : "=r"(r0), "=r"(r1), "=r"(r2), "=r"(r3) : "r"(addr));
}
__device__ __forceinline__ void mma16816(float* d, const uint32_t* a, const uint32_t* b) {
    asm volatile(
        "mma.sync.aligned.m16n8k16.row.col.f32.f16.f16.f32 "
        "{%0,%1,%2,%3}, {%4,%5,%6,%7}, {%8,%9}, {%0,%1,%2,%3};"
        : "+f"(d[0]), "+f"(d[1]), "+f"(d[2]), "+f"(d[3])
        : "r"(a[0]), "r"(a[1]), "r"(a[2]), "r"(a[3]), "r"(b[0]), "r"(b[1]));
}

// one chunk: A_hi, A_lo, B_hi tiles (128 rows x 32 fp16 each); 6 cp16/thread
__device__ __forceinline__ void load_chunk(int c, uint32_t st, int bm, int bu, int tid) {
    const int koff = (c & 63) * BK;
    const __half *Ah, *Al, *Bh;
    if (c < 64) { Ah = g_xh; Al = g_xl; Bh = g_wh; }
    else        { Ah = g_hh; Al = g_hl; Bh = g_uh; }
    #pragma unroll
    for (int i = 0; i < 2; ++i) {
        int e = i * 256 + tid;                 // 512 16B units per tile
        int r = e >> 2, ch = e & 3;
        uint32_t d = st + r * 64 + (((ch ^ ((r >> 1) & 3))) << 4);
        size_t ga = (size_t)(bm + r) * KD + koff + ch * 8;
        cp16(d, Ah + ga);
        cp16(d + TILEB, Al + ga);
        int u = r >> 2, g = r & 3;             // B row r: n = u*4 + g (gate-minor)
        size_t gb = ((size_t)(g * NUNITS + bu + u)) * KD + koff + ch * 8;
        cp16(d + 2 * TILEB, Bh + gb);
    }
}

__global__ void __launch_bounds__(256, 2)
lstm_mma(const float* __restrict__ pre_c, float* __restrict__ out)
{
    extern __shared__ char smem[];
    const uint32_t sb = smem_u32(smem);
    const int tid = threadIdx.x, lane = tid & 31, wid = tid >> 5;
    const int bm = blockIdx.y * BM, bu = blockIdx.x * 32;
    const int wm = (wid >> 2) * 64, wn = (wid & 3) * 32;

    const uint32_t mb = sb + NSTG * STAGEB;    // mbarrier block
    // full[s] = mb + 8*s ; free[s] = mb + 32 + 8*s
    if (tid == 0) {
        #pragma unroll
        for (int s = 0; s < NSTG; ++s) { mbar_init(mb + 8 * s, 256); mbar_init(mb + 32 + 8 * s, 256); }
    }
    __syncthreads();

    float acc[4][4][4];
    #pragma unroll
    for (int i = 0; i < 4; ++i)
        #pragma unroll
        for (int j = 0; j < 4; ++j)
            #pragma unroll
            for (int k = 0; k < 4; ++k) acc[i][j][k] = 0.f;

    // prologue: load chunks 0..2, arm full[0..2]
    #pragma unroll
    for (int c0 = 0; c0 < 3; ++c0) {
        load_chunk(c0, sb + c0 * STAGEB, bm, bu, tid);
        cp_arrive_noinc(mb + 8 * c0);
    }

    // A frag: row = wm + i*16 + (lane&15); logical 16B chunk ch = (lane>>4) + 2s
    const int rA = wm + (lane & 15);
    const uint32_t aBase = (uint32_t)rA * 64;
    const int selA = (rA >> 1) & 3;
    const int chA0 = lane >> 4;
    // B frag: row = wn + ((lane>>4)<<3) + (lane&7); ch = ((lane>>3)&1) + 2s
    const int rB = wn + (((lane >> 4) << 3) + (lane & 7));
    const uint32_t bBase = (uint32_t)rB * 64;
    const int selB = (rB >> 1) & 3;
    const int chB0 = (lane >> 3) & 1;

    #pragma unroll 1
    for (int c = 0; c < NCH; ++c) {
        const int s = c & 3;
        const uint32_t stv = sb + s * STAGEB;

        // ---- consume chunk c ----
        mbar_wait(mb + 8 * s, (uint32_t)((c >> 2) & 1));

        const uint32_t aH = stv + aBase;
        const uint32_t bH = stv + 2 * TILEB + bBase;
        #pragma unroll
        for (int sk = 0; sk < 2; ++sk) {
            const uint32_t offB = (uint32_t)(((chB0 + 2 * sk) ^ selB) << 4);
            const uint32_t offA = (uint32_t)(((chA0 + 2 * sk) ^ selA) << 4);
            uint32_t bh[4][2];
            #pragma unroll
            for (int jj = 0; jj < 2; ++jj) {
                uint32_t ad = bH + jj * 1024 + offB;
                ldsm4(bh[2*jj][0], bh[2*jj][1], bh[2*jj+1][0], bh[2*jj+1][1], ad);
            }
            #pragma unroll
            for (int i = 0; i < 4; ++i) {
                uint32_t ah[4], al[4];
                uint32_t ad = aH + i * 1024 + offA;
                ldsm4(ah[0], ah[1], ah[2], ah[3], ad);
                ldsm4(al[0], al[1], al[2], al[3], ad + TILEB);
                #pragma unroll
                for (int j = 0; j < 4; ++j) {
                    mma16816(acc[i][j], ah, bh[j]);
                    mma16816(acc[i][j], al, bh[j]);
                }
            }
        }
        mbar_arrive(mb + 32 + 8 * s);          // stage s free (this thread)

        // ---- produce chunk c+3 ----
        const int cp = c + 3;
        if (cp < NCH) {
            const int s2 = cp & 3;
            if (cp >= NSTG) mbar_wait(mb + 32 + 8 * s2, (uint32_t)(((cp >> 2) - 1) & 1));
            load_chunk(cp, sb + s2 * STAGEB, bm, bu, tid);
            cp_arrive_noinc(mb + 8 * s2);
        }
    }
    __syncthreads();   // all warps done; smem reusable

    // ---------------- fused LSTM epilogue ----------------
    const size_t CO = (size_t)NBATCH * NUNITS;
    float pcv[16];
    #pragma unroll
    for (int i = 0; i < 16; ++i) {
        int idx = i * 256 + tid;
        int m = idx >> 5, u = idx & 31;
        pcv[i] = pre_c[(size_t)(bm + m) * NUNITS + bu + u];
    }
    float* S = (float*)smem;                 // [8 warps][64 m][32 n-local]
    const uint32_t base = wid * 2048;
    #pragma unroll
    for (int i = 0; i < 4; ++i)
        #pragma unroll
        for (int j = 0; j < 4; ++j) {
            int r0 = i * 16 + (lane >> 2), c0 = j * 8 + (lane & 3) * 2;
            *(float2*)&S[base + r0 * 32 + c0]       = make_float2(acc[i][j][0], acc[i][j][1]);
            *(float2*)&S[base + (r0 + 8) * 32 + c0] = make_float2(acc[i][j][2], acc[i][j][3]);
        }
    __syncthreads();

    #pragma unroll
    for (int i = 0; i < 16; ++i) {
        int idx = i * 256 + tid;
        int m = idx >> 5, u = idx & 31;
        int wreg = (m >> 6) * 4 + (u >> 3);
        float4 gt = *(float4*)&S[wreg * 2048 + (m & 63) * 32 + (u & 7) * 4];
        float it = 1.f / (1.f + __expf(-gt.x));
        float ft = 1.f / (1.f + __expf(-gt.y));
        float ot = 1.f / (1.f + __expf(-gt.z));
        float nt = tanhf(gt.w);
        size_t o = (size_t)(bm + m) * NUNITS + bu + u;
        float cc = ft * pcv[i] + it * nt;
        float hh = ot * tanhf(cc);
        out[o]      = hh;
        out[CO + o] = cc;
    }
}

// -------- fp32 -> fp16 split / round, all tensors in one launch --------
__global__ void split_all(const float* __restrict__ x, const float* __restrict__ ph,
                          const float* __restrict__ W, const float* __restrict__ U)
{
    const int SEG = NBATCH * KD / 4;               // 2M float4 per x-like tensor
    int i = blockIdx.x * 256 + threadIdx.x;
    if (i < 2 * SEG) {
        // activations: hi + lo split
        const float* s; __half *hi, *lo; int off;
        if (i < SEG) { s = x;  hi = g_xh; lo = g_xl; off = i; }
        else         { s = ph; hi = g_hh; lo = g_hl; off = i - SEG; }
        float4 v = reinterpret_cast<const float4*>(s)[off];
        float f[4] = {v.x, v.y, v.z, v.w};
        unsigned short hs[4], ls[4];
        #pragma unroll
        for (int k = 0; k < 4; ++k) {
            __half h = __float2half_rn(f[k]);
            __half l = __float2half_rn(f[k] - __half2float(h));
            hs[k] = *reinterpret_cast<unsigned short*>(&h);
            ls[k] = *reinterpret_cast<unsigned short*>(&l);
        }
        reinterpret_cast<ushort4*>(hi)[off] = make_ushort4(hs[0], hs[1], hs[2], hs[3]);
        reinterpret_cast<ushort4*>(lo)[off] = make_ushort4(ls[0], ls[1], ls[2], ls[3]);
    } else {
        // weights: round to fp16 only
        const float* s; __half* hi; int off;
        if (i < 4 * SEG) { s = W; hi = g_wh; off = i - 2 * SEG; }
        else             { s = U; hi = g_uh; off = i - 4 * SEG; }
        float4 v = reinterpret_cast<const float4*>(s)[off];
        float f[4] = {v.x, v.y, v.z, v.w};
        unsigned short hs[4];
        #pragma unroll
        for (int k = 0; k < 4; ++k) {
            __half h = __float2half_rn(f[k]);
            hs[k] = *reinterpret_cast<unsigned short*>(&h);
        }
        reinterpret_cast<ushort4*>(hi)[off] = make_ushort4(hs[0], hs[1], hs[2], hs[3]);
    }
}

extern "C" void kernel_launch(void* const* d_in, const int* in_sizes, int n_in,
                              void* d_out, int out_size)
{
    const float* pre_layer = (const float*)d_in[0];  // (2, 4096, 2048)
    const float* x         = (const float*)d_in[1];  // (4096, 2048)
    const float* W         = (const float*)d_in[2];  // (4, 2048, 2048)
    const float* U         = (const float*)d_in[3];  // (4, 2048, 2048)
    float* out             = (float*)d_out;

    const int SEG = NBATCH * KD / 4;                 // 2M
    const int total = 6 * SEG;                       // x(1) + h(1) + W(2) + U(2)
    split_all<<<total / 256, 256>>>(x, pre_layer, W, U);

    cudaFuncSetAttribute(lstm_mma, cudaFuncAttributeMaxDynamicSharedMemorySize, SMEMB);
    const float* pre_c = pre_layer + (size_t)NBATCH * NUNITS;
    lstm_mma<<<dim3(NUNITS / 32, NBATCH / BM), 256, SMEMB>>>(pre_c, out);
}

// round 11
// speedup vs baseline: 2.9867x; 1.7356x over previous
#include <cuda_runtime.h>
#include <cuda_fp16.h>
#include <stdint.h>
#include <math.h>

// LSTM cell: gates = x@W^T + pre_h@U^T via pure-fp16 mma.sync (single term).
// Both operands rounded to fp16; fp32 accumulate. rel_err ~ 2^-12 per operand.
// N = 128 = 32 units x 4 gates, gate-minor (n = u*4 + g).
// 4-stage lock-free mbarrier ring, 2 CTAs/SM.

#define NBATCH 4096
#define NUNITS 2048
#define KD     2048
#define BM 128
#define BK 32
#define NCH 128                // 2 phases * (2048/32)
#define NSTG 4
#define TILEB (128*64)         // 8192 B (128 rows x 32 fp16)
#define STAGEB (2*TILEB)       // Ah, Bh = 16384 B
#define SMEMB (NSTG*STAGEB + 64)

// -------- fp16 scratch --------
__device__ __align__(128) __half g_xh[(size_t)NBATCH*KD];
__device__ __align__(128) __half g_hh[(size_t)NBATCH*KD];
__device__ __align__(128) __half g_wh[(size_t)4*NUNITS*KD];
__device__ __align__(128) __half g_uh[(size_t)4*NUNITS*KD];

__device__ __forceinline__ uint32_t smem_u32(const void* p) {
    uint32_t a;
    asm("{ .reg .u64 t; cvta.to.shared.u64 t, %1; cvt.u32.u64 %0, t; }" : "=r"(a) : "l"(p));
    return a;
}
__device__ __forceinline__ void cp16(uint32_t dst, const void* src) {
    asm volatile("cp.async.cg.shared.global [%0], [%1], 16;" :: "r"(dst), "l"(src));
}
__device__ __forceinline__ void mbar_init(uint32_t m, uint32_t cnt) {
    asm volatile("mbarrier.init.shared.b64 [%0], %1;" :: "r"(m), "r"(cnt) : "memory");
}
__device__ __forceinline__ void mbar_arrive(uint32_t m) {
    asm volatile("mbarrier.arrive.shared.b64 _, [%0];" :: "r"(m) : "memory");
}
__device__ __forceinline__ void cp_arrive_noinc(uint32_t m) {
    asm volatile("cp.async.mbarrier.arrive.noinc.shared.b64 [%0];" :: "r"(m) : "memory");
}
__device__ __forceinline__ void mbar_wait(uint32_t m, uint32_t parity) {
    asm volatile(
        "{\n\t.reg .pred P;\n\t"
        "LAB%=:\n\t"
        "mbarrier.try_wait.parity.acquire.cta.shared::cta.b64 P, [%0], %1, 0x989680;\n\t"
        "@!P bra LAB%=;\n\t}"
        :: "r"(m), "r"(parity) : "memory");
}
__device__ __forceinline__ void ldsm4(uint32_t& r0, uint32_t& r1, uint32_t& r2, uint32_t& r3,
                                      uint32_t addr) {
    asm volatile("ldmatrix.sync.aligned.m8n8.x4.shared.b16 {%0,%1,%2,%3}, [%4];"
                 : "=r"(r0), "=r"(r1), "=r"(r2), "=r"(r3) : "r"(addr));
}
__device__ __forceinline__ void mma16816(float* d, const uint32_t* a, const uint32_t* b) {
    asm volatile(
        "mma.sync.aligned.m16n8k16.row.col.f32.f16.f16.f32 "
        "{%0,%1,%2,%3}, {%4,%5,%6,%7}, {%8,%9}, {%0,%1,%2,%3};"
        : "+f"(d[0]), "+f"(d[1]), "+f"(d[2]), "+f"(d[3])
        : "r"(a[0]), "r"(a[1]), "r"(a[2]), "r"(a[3]), "r"(b[0]), "r"(b[1]));
}

// one chunk: Ah, Bh tiles (128 rows x 32 fp16 each); 4 cp16/thread
__device__ __forceinline__ void load_chunk(int c, uint32_t st, int bm, int bu, int tid) {
    const int koff = (c & 63) * BK;
    const __half *Ah, *Bh;
    if (c < 64) { Ah = g_xh; Bh = g_wh; }
    else        { Ah = g_hh; Bh = g_uh; }
    #pragma unroll
    for (int i = 0; i < 2; ++i) {
        int e = i * 256 + tid;                 // 512 16B units per tile
        int r = e >> 2, ch = e & 3;
        uint32_t d = st + r * 64 + (((ch ^ ((r >> 1) & 3))) << 4);
        size_t ga = (size_t)(bm + r) * KD + koff + ch * 8;
        cp16(d, Ah + ga);
        int u = r >> 2, g = r & 3;             // B row r: n = u*4 + g (gate-minor)
        size_t gb = ((size_t)(g * NUNITS + bu + u)) * KD + koff + ch * 8;
        cp16(d + TILEB, Bh + gb);
    }
}

__global__ void __launch_bounds__(256, 2)
lstm_mma(const float* __restrict__ pre_c, float* __restrict__ out)
{
    extern __shared__ char smem[];
    const uint32_t sb = smem_u32(smem);
    const int tid = threadIdx.x, lane = tid & 31, wid = tid >> 5;
    const int bm = blockIdx.y * BM, bu = blockIdx.x * 32;
    const int wm = (wid >> 2) * 64, wn = (wid & 3) * 32;

    const uint32_t mb = sb + NSTG * STAGEB;    // mbarrier block
    // full[s] = mb + 8*s ; free[s] = mb + 32 + 8*s
    if (tid == 0) {
        #pragma unroll
        for (int s = 0; s < NSTG; ++s) { mbar_init(mb + 8 * s, 256); mbar_init(mb + 32 + 8 * s, 256); }
    }
    __syncthreads();

    float acc[4][4][4];
    #pragma unroll
    for (int i = 0; i < 4; ++i)
        #pragma unroll
        for (int j = 0; j < 4; ++j)
            #pragma unroll
            for (int k = 0; k < 4; ++k) acc[i][j][k] = 0.f;

    // prologue: load chunks 0..2, arm full[0..2]
    #pragma unroll
    for (int c0 = 0; c0 < 3; ++c0) {
        load_chunk(c0, sb + c0 * STAGEB, bm, bu, tid);
        cp_arrive_noinc(mb + 8 * c0);
    }

    // A frag: row = wm + i*16 + (lane&15); logical 16B chunk ch = (lane>>4) + 2s
    const int rA = wm + (lane & 15);
    const uint32_t aBase = (uint32_t)rA * 64;
    const int selA = (rA >> 1) & 3;
    const int chA0 = lane >> 4;
    // B frag: row = wn + ((lane>>4)<<3) + (lane&7); ch = ((lane>>3)&1) + 2s
    const int rB = wn + (((lane >> 4) << 3) + (lane & 7));
    const uint32_t bBase = (uint32_t)rB * 64;
    const int selB = (rB >> 1) & 3;
    const int chB0 = (lane >> 3) & 1;

    #pragma unroll 1
    for (int c = 0; c < NCH; ++c) {
        const int s = c & 3;
        const uint32_t stv = sb + s * STAGEB;

        // ---- consume chunk c ----
        mbar_wait(mb + 8 * s, (uint32_t)((c >> 2) & 1));

        const uint32_t aH = stv + aBase;
        const uint32_t bH = stv + TILEB + bBase;
        #pragma unroll
        for (int sk = 0; sk < 2; ++sk) {
            const uint32_t offB = (uint32_t)(((chB0 + 2 * sk) ^ selB) << 4);
            const uint32_t offA = (uint32_t)(((chA0 + 2 * sk) ^ selA) << 4);
            uint32_t bh[4][2];
            #pragma unroll
            for (int jj = 0; jj < 2; ++jj) {
                uint32_t ad = bH + jj * 1024 + offB;
                ldsm4(bh[2*jj][0], bh[2*jj][1], bh[2*jj+1][0], bh[2*jj+1][1], ad);
            }
            #pragma unroll
            for (int i = 0; i < 4; ++i) {
                uint32_t ah[4];
                uint32_t ad = aH + i * 1024 + offA;
                ldsm4(ah[0], ah[1], ah[2], ah[3], ad);
                #pragma unroll
                for (int j = 0; j < 4; ++j)
                    mma16816(acc[i][j], ah, bh[j]);
            }
        }
        mbar_arrive(mb + 32 + 8 * s);          // stage s free (this thread)

        // ---- produce chunk c+3 ----
        const int cp = c + 3;
        if (cp < NCH) {
            const int s2 = cp & 3;
            if (cp >= NSTG) mbar_wait(mb + 32 + 8 * s2, (uint32_t)(((cp >> 2) - 1) & 1));
            load_chunk(cp, sb + s2 * STAGEB, bm, bu, tid);
            cp_arrive_noinc(mb + 8 * s2);
        }
    }
    __syncthreads();   // all warps done; smem reusable

    // ---------------- fused LSTM epilogue ----------------
    const size_t CO = (size_t)NBATCH * NUNITS;
    float pcv[16];
    #pragma unroll
    for (int i = 0; i < 16; ++i) {
        int idx = i * 256 + tid;
        int m = idx >> 5, u = idx & 31;
        pcv[i] = pre_c[(size_t)(bm + m) * NUNITS + bu + u];
    }
    float* S = (float*)smem;                 // [8 warps][64 m][32 n-local]
    const uint32_t base = wid * 2048;
    #pragma unroll
    for (int i = 0; i < 4; ++i)
        #pragma unroll
        for (int j = 0; j < 4; ++j) {
            int r0 = i * 16 + (lane >> 2), c0 = j * 8 + (lane & 3) * 2;
            *(float2*)&S[base + r0 * 32 + c0]       = make_float2(acc[i][j][0], acc[i][j][1]);
            *(float2*)&S[base + (r0 + 8) * 32 + c0] = make_float2(acc[i][j][2], acc[i][j][3]);
        }
    __syncthreads();

    #pragma unroll
    for (int i = 0; i < 16; ++i) {
        int idx = i * 256 + tid;
        int m = idx >> 5, u = idx & 31;
        int wreg = (m >> 6) * 4 + (u >> 3);
        float4 gt = *(float4*)&S[wreg * 2048 + (m & 63) * 32 + (u & 7) * 4];
        float it = 1.f / (1.f + __expf(-gt.x));
        float ft = 1.f / (1.f + __expf(-gt.y));
        float ot = 1.f / (1.f + __expf(-gt.z));
        float nt = tanhf(gt.w);
        size_t o = (size_t)(bm + m) * NUNITS + bu + u;
        float cc = ft * pcv[i] + it * nt;
        float hh = ot * tanhf(cc);
        out[o]      = hh;
        out[CO + o] = cc;
    }
}

// -------- fp32 -> fp16 round, all tensors in one launch --------
__global__ void split_all(const float* __restrict__ x, const float* __restrict__ ph,
                          const float* __restrict__ W, const float* __restrict__ U)
{
    const int SEG = NBATCH * KD / 4;               // 2M float4 per x-like tensor
    int i = blockIdx.x * 256 + threadIdx.x;
    const float* s; __half* hi; int off;
    if (i < SEG)            { s = x;  hi = g_xh; off = i; }
    else if (i < 2 * SEG)   { s = ph; hi = g_hh; off = i - SEG; }
    else if (i < 4 * SEG)   { s = W;  hi = g_wh; off = i - 2 * SEG; }
    else                    { s = U;  hi = g_uh; off = i - 4 * SEG; }
    float4 v = reinterpret_cast<const float4*>(s)[off];
    __half2 h0 = __floats2half2_rn(v.x, v.y);
    __half2 h1 = __floats2half2_rn(v.z, v.w);
    uint32_t u0 = *reinterpret_cast<uint32_t*>(&h0);
    uint32_t u1 = *reinterpret_cast<uint32_t*>(&h1);
    reinterpret_cast<uint2*>(hi)[off] = make_uint2(u0, u1);
}

extern "C" void kernel_launch(void* const* d_in, const int* in_sizes, int n_in,
                              void* d_out, int out_size)
{
    const float* pre_layer = (const float*)d_in[0];  // (2, 4096, 2048)
    const float* x         = (const float*)d_in[1];  // (4096, 2048)
    const float* W         = (const float*)d_in[2];  // (4, 2048, 2048)
    const float* U         = (const float*)d_in[3];  // (4, 2048, 2048)
    float* out             = (float*)d_out;

    const int SEG = NBATCH * KD / 4;                 // 2M
    const int total = 6 * SEG;                       // x(1) + h(1) + W(2) + U(2)
    split_all<<<total / 256, 256>>>(x, pre_layer, W, U);

    cudaFuncSetAttribute(lstm_mma, cudaFuncAttributeMaxDynamicSharedMemorySize, SMEMB);
    const float* pre_c = pre_layer + (size_t)NBATCH * NUNITS;
    lstm_mma<<<dim3(NUNITS / 32, NBATCH / BM), 256, SMEMB>>>(pre_c, out);
}